// round 1
// baseline (speedup 1.0000x reference)
#include <cuda_runtime.h>

#define NB 8
#define NS 4096
#define NH 8
#define ND 128
#define ROW (NH * ND)            // 1024 floats per (token) row
#define VPR (ROW / 4)            // 256 float4 per row
#define MAX_TOTAL (NB * NS)      // 32768 rows per cache
#define CACHE_F (MAX_TOTAL * ROW)        // 33554432 floats per cache
#define CACHE_V (MAX_TOTAL * VPR)        // 8388608 float4 per cache
#define TOTAL_V (2 * CACHE_V)            // 16777216 float4 (k + v)

__device__ int g_cumsum[NB + 1];

// Prologue: compute cumsum on device (B=8, trivial) and emit the small
// integer outputs as numeric floats at the tail of d_out.
__global__ void prep_kernel(const int* __restrict__ seq_lens, float* __restrict__ out) {
    if (threadIdx.x == 0 && blockIdx.x == 0) {
        float* seq_out = out + 2 * (long long)CACHE_F;       // [NB]
        float* cum_out = seq_out + NB;                        // [NB+1]
        int c = 0;
        g_cumsum[0] = 0;
        cum_out[0] = 0.0f;
        #pragma unroll
        for (int i = 0; i < NB; i++) {
            int sl = seq_lens[i];
            seq_out[i] = (float)sl;
            c += sl;
            g_cumsum[i + 1] = c;
            cum_out[i + 1] = (float)c;
        }
    }
}

// Main pass: for every float4 of both output caches, gather from the valid
// source row (found via the 9-entry cumsum) or write zero. One coalesced
// write over 256 MB, one coalesced read over the valid ~half of the input.
__global__ void __launch_bounds__(256) pack_kernel(
    const float4* __restrict__ k_src,
    const float4* __restrict__ v_src,
    float4* __restrict__ out)
{
    __shared__ int cs[NB + 1];
    if (threadIdx.x <= NB) cs[threadIdx.x] = g_cumsum[threadIdx.x];
    __syncthreads();

    int i = blockIdx.x * 256 + threadIdx.x;
    if (i >= TOTAL_V) return;

    int which = (i >= CACHE_V) ? 1 : 0;          // 0 = K cache, 1 = V cache
    int j = i - which * CACHE_V;
    int row = j >> 8;                             // j / VPR
    int c   = j & (VPR - 1);                      // j % VPR

    float4 val;
    if (row < cs[NB]) {
        int b = 0;
        #pragma unroll
        for (int bb = 1; bb < NB; bb++)
            if (row >= cs[bb]) b = bb;
        int t = row - cs[b];
        const float4* src = which ? v_src : k_src;
        val = src[(b * NS + t) * VPR + c];
    } else {
        val = make_float4(0.f, 0.f, 0.f, 0.f);
    }
    out[i] = val;
}

extern "C" void kernel_launch(void* const* d_in, const int* in_sizes, int n_in,
                              void* d_out, int out_size) {
    const float* key_states   = (const float*)d_in[0];
    const float* value_states = (const float*)d_in[1];
    const int*   seq_lens     = (const int*)d_in[2];
    float* out = (float*)d_out;

    prep_kernel<<<1, 32>>>(seq_lens, out);

    int blocks = TOTAL_V / 256;  // 65536
    pack_kernel<<<blocks, 256>>>(
        (const float4*)key_states, (const float4*)value_states, (float4*)out);
}